// round 1
// baseline (speedup 1.0000x reference)
#include <cuda_runtime.h>

// Problem constants (fixed by the reference)
static constexpr int TOKEN_NUM  = 300;
static constexpr int PATCH_SIZE = 256;
static constexpr int HALF       = PATCH_SIZE * TOKEN_NUM;   // 76800
static constexpr int TOTAL      = 4 * 2 * HALF;             // 614400
static constexpr int OUT_ELEMS  = 2 * TOTAL;                // 1228800

__global__ void zero_out_kernel(float4* __restrict__ out) {
    int i = blockIdx.x * blockDim.x + threadIdx.x;
    if (i < OUT_ELEMS / 4) out[i] = make_float4(0.f, 0.f, 0.f, 0.f);
}

__global__ void hist_kernel(const float* __restrict__ x,
                            float* __restrict__ out,
                            int n) {
    // Divisors computed in double then cast to f32, matching Python scalar -> f32 weak typing
    const float DIVW = (float)(319.0 / 20.0 + 0.0001);   // W/PW + B
    const float DIVH = (float)(239.0 / 15.0 + 0.0001);   // H/PH + B

    const float t0 = __ldg(x);
    const float tl = __ldg(x + 4 * (size_t)(n - 1));
    const float inv_b = 1.0f / (tl - t0 + 0.0001f);      // for wt
    const float inv_d = 4.0f / (tl - t0 + 1.0f);         // TIME_DIV / (range + 1)

    int i = blockIdx.x * blockDim.x + threadIdx.x;
    if (i >= n) return;

    const float4 e = ((const float4*)x)[i];   // (t, xs, ys, p)
    const float t  = e.x;
    const float xs = e.y;
    const float ys = e.z;
    const float p  = e.w;

    const float w  = (p != 2.0f) ? 1.0f : 0.0f;
    const float wt = (t - t0) * inv_b;

    const float posf = floorf(xs / DIVW) + floorf(ys / DIVH) * 20.0f;
    const float tokf = floorf(fmodf(xs, DIVW)) + floorf(fmodf(ys, DIVH)) * 16.0f;
    const float dtf  = floorf((t - t0) * inv_d);

    // clip to [0, bins] (upper bound INCLUSIVE, matching jnp.clip(x, 0, bins))
    int d  = min(max((int)dtf,  0), 4);
    int pi = min(max((int)p,    0), 2);
    int tk = min(max((int)tokf, 0), 256);
    int ps = min(max((int)posf, 0), 300);

    int l = d * (2 * HALF) + pi * HALF + tk * TOKEN_NUM + ps;
    if (l >= TOTAL) return;   // segment_sum drops out-of-range segments

    // output layout: stack([h_w, h_wt], axis=2) over (TIME_DIV,2, 2, PATCH_SIZE,TOKEN_NUM)
    int hi   = l / HALF;          // (dtime*2 + p) in [0,8)
    int lo   = l - hi * HALF;
    int base = hi * (2 * HALF) + lo;

    atomicAdd(out + base,        w);
    atomicAdd(out + base + HALF, wt);
}

extern "C" void kernel_launch(void* const* d_in, const int* in_sizes, int n_in,
                              void* d_out, int out_size) {
    const float* x = (const float*)d_in[0];
    float* out = (float*)d_out;
    const int n = in_sizes[0] / 4;   // events

    zero_out_kernel<<<(OUT_ELEMS / 4 + 255) / 256, 256>>>((float4*)out);
    hist_kernel<<<(n + 255) / 256, 256>>>(x, out, n);
}

// round 2
// speedup vs baseline: 1.6251x; 1.6251x over previous
#include <cuda_runtime.h>

// Problem constants (fixed by the reference)
static constexpr int TOKEN_NUM  = 300;
static constexpr int PATCH_SIZE = 256;
static constexpr int HALF       = PATCH_SIZE * TOKEN_NUM;   // 76800
static constexpr int TOTAL      = 4 * 2 * HALF;             // 614400
static constexpr int OUT_ELEMS  = 2 * TOTAL;                // 1228800

// Fixed-point scale for wt accumulation (wt in [0,1)); headroom: counts per bin
// are Poisson(~27) << 2^(32-21)=2048, so no carry into the count field.
static constexpr float WT_SCALE     = 2097152.0f;           // 2^21
static constexpr float WT_INV_SCALE = 1.0f / 2097152.0f;

__device__ unsigned long long g_scratch[TOTAL];

__global__ void zero_scratch_kernel() {
    int i = blockIdx.x * blockDim.x + threadIdx.x;
    if (i < TOTAL / 2) ((ulonglong2*)g_scratch)[i] = make_ulonglong2(0ull, 0ull);
}

__global__ void hist_kernel(const float* __restrict__ x, int n) {
    const float DIVW = (float)(319.0 / 20.0 + 0.0001);   // W/PW + B
    const float DIVH = (float)(239.0 / 15.0 + 0.0001);   // H/PH + B

    const float t0 = __ldg(x);
    const float tl = __ldg(x + 4 * (size_t)(n - 1));
    const float inv_b = 1.0f / (tl - t0 + 0.0001f);      // for wt
    const float inv_d = 4.0f / (tl - t0 + 1.0f);         // TIME_DIV / (range + 1)

    int i = blockIdx.x * blockDim.x + threadIdx.x;
    if (i >= n) return;

    const float4 e = ((const float4*)x)[i];   // (t, xs, ys, p)
    const float t  = e.x;
    const float xs = e.y;
    const float ys = e.z;
    const float p  = e.w;

    const unsigned int w = (p != 2.0f) ? 1u : 0u;
    const float wt = (t - t0) * inv_b;

    const float posf = floorf(xs / DIVW) + floorf(ys / DIVH) * 20.0f;
    const float tokf = floorf(fmodf(xs, DIVW)) + floorf(fmodf(ys, DIVH)) * 16.0f;
    const float dtf  = floorf((t - t0) * inv_d);

    // clip to [0, bins] (upper bound INCLUSIVE, matching jnp.clip(x, 0, bins))
    int d  = min(max((int)dtf,  0), 4);
    int pi = min(max((int)p,    0), 2);
    int tk = min(max((int)tokf, 0), 256);
    int ps = min(max((int)posf, 0), 300);

    int l = d * (2 * HALF) + pi * HALF + tk * TOKEN_NUM + ps;
    if (l >= TOTAL) return;   // segment_sum drops out-of-range segments

    // pack: low 32 = count, high 32 = fixed-point wt sum
    unsigned int wtq = (unsigned int)(wt * WT_SCALE + 0.5f);
    unsigned long long pkt = (unsigned long long)w
                           | ((unsigned long long)wtq << 32);
    atomicAdd(&g_scratch[l], pkt);
}

__global__ void finalize_kernel(float* __restrict__ out) {
    int l = blockIdx.x * blockDim.x + threadIdx.x;
    if (l >= TOTAL) return;

    unsigned long long v = g_scratch[l];
    float cnt = (float)(unsigned int)(v & 0xFFFFFFFFull);
    float wts = (float)(unsigned int)(v >> 32) * WT_INV_SCALE;

    // output layout: stack([h_w, h_wt], axis=2) over (TIME_DIV,2, 2, PS,TN)
    int hi   = l / HALF;          // (dtime*2 + p) in [0,8)
    int lo   = l - hi * HALF;
    int base = hi * (2 * HALF) + lo;

    out[base]        = cnt;
    out[base + HALF] = wts;
}

extern "C" void kernel_launch(void* const* d_in, const int* in_sizes, int n_in,
                              void* d_out, int out_size) {
    const float* x = (const float*)d_in[0];
    float* out = (float*)d_out;
    const int n = in_sizes[0] / 4;   // events

    zero_scratch_kernel<<<(TOTAL / 2 + 255) / 256, 256>>>();
    hist_kernel<<<(n + 255) / 256, 256>>>(x, n);
    finalize_kernel<<<(TOTAL + 255) / 256, 256>>>(out);
}